// round 7
// baseline (speedup 1.0000x reference)
#include <cuda_runtime.h>
#include <cstdint>

#define GRID_N   7
#define NB       2
#define NC       20
#define IS       8
#define DCH      30
#define L_BOX    5.0f
#define L_NEG    0.5f

#define TPB      128
#define WARPS    (TPB / 32)
#define MAX_BLOCKS 8192

__device__ double g_partials[MAX_BLOCKS];
__device__ unsigned int g_count = 0;

__device__ __forceinline__ void cp_async16(uint32_t dst, const void* src) {
    asm volatile("cp.async.cg.shared.global [%0], [%1], 16;\n" :: "r"(dst), "l"(src));
}
__device__ __forceinline__ void cp_async_wait_all() {
    asm volatile("cp.async.commit_group;\ncp.async.wait_group 0;\n" ::: "memory");
}

// 1 + exp(-|x|)  (the log1p argument term)
__device__ __forceinline__ float bce_t(float x) {
    return 1.0f + __expf(-fabsf(x));
}

__device__ __forceinline__ float box_loss_f(const float* pb, const float* gb) {
    float dx = pb[0] - gb[0];
    float dy = pb[1] - gb[1];
    float sw = sqrtf(fabsf(pb[2])) - sqrtf(gb[2]);
    float sh = sqrtf(fabsf(pb[3])) - sqrtf(gb[3]);
    return dx * dx + dy * dy + sw * sw + sh * sh;
}

// pc/gc point at one cell's 30 floats (smem in the fast path, gmem in the tail).
__device__ __forceinline__ float cell_loss(const float* __restrict__ pc,
                                           const float* __restrict__ gc,
                                           int cellIdx) {
    const float2* pc2 = reinterpret_cast<const float2*>(pc);
    const float2* gc2 = reinterpret_cast<const float2*>(gc);
    float2 pb0 = pc2[0], pb1 = pc2[1], pb2v = pc2[2], pb3 = pc2[3];
    float2 gb0 = gc2[0], gb1 = gc2[1], gb2v = gc2[2], gb3 = gc2[3];
    float2 pconf = pc2[4];          // p[8], p[9]
    float2 gconf = gc2[4];          // g[8], g[9]

    if (gconf.x > 0.0f) {
        // ================= positive cell =================
        float pv[IS] = {pb0.x, pb0.y, pb1.x, pb1.y, pb2v.x, pb2v.y, pb3.x, pb3.y};
        float gv[IS] = {gb0.x, gb0.y, gb1.x, gb1.y, gb2v.x, gb2v.y, gb3.x, gb3.y};

        // ---- classification: linear part + single log of product ----
        const float2* pcl2 = reinterpret_cast<const float2*>(pc + NB * 5);
        const float2* gcl2 = reinterpret_cast<const float2*>(gc + NB * 5);
        float lin = 0.0f;
        float prod = 1.0f;
        #pragma unroll
        for (int i = 0; i < NC / 2; i++) {
            float2 a = pcl2[i];
            float2 b = gcl2[i];
            lin  += fmaxf(a.x, 0.f) - a.x * b.x + fmaxf(a.y, 0.f) - a.y * b.y;
            prod *= bce_t(a.x) * bce_t(a.y);
        }
        float cls = lin + __logf(prod);

        // ---- cell coordinates: cr = (col, row) ----
        int cell = cellIdx % (GRID_N * GRID_N);
        float col = (float)(cell % GRID_N);
        float row = (float)(cell / GRID_N);

        // ---- box offsets ----
        float poff[NB][4], gbox[NB][4];
        #pragma unroll
        for (int b = 0; b < NB; b++) {
            poff[b][0] = __fdividef(1.0f, 1.0f + __expf(-pv[4 * b + 0]));
            poff[b][1] = __fdividef(1.0f, 1.0f + __expf(-pv[4 * b + 1]));
            poff[b][2] = pv[4 * b + 2];
            poff[b][3] = pv[4 * b + 3];
            gbox[b][0] = gv[4 * b + 0];
            gbox[b][1] = gv[4 * b + 1];
            gbox[b][2] = gv[4 * b + 2];
            gbox[b][3] = gv[4 * b + 3];
        }

        // ---- ltrb boxes ----
        float pl[NB][4], gl[NB][4];
        #pragma unroll
        for (int b = 0; b < NB; b++) {
            float cx = (poff[b][0] + col) * (1.0f / GRID_N);
            float cy = (poff[b][1] + row) * (1.0f / GRID_N);
            float w  = poff[b][2], h = poff[b][3];
            pl[b][0] = cx - w * 0.5f; pl[b][1] = cy - h * 0.5f;
            pl[b][2] = cx + w * 0.5f; pl[b][3] = cy + h * 0.5f;
            float gx = (gbox[b][0] + col) * (1.0f / GRID_N);
            float gy = (gbox[b][1] + row) * (1.0f / GRID_N);
            float gw = gbox[b][2], gh = gbox[b][3];
            gl[b][0] = gx - gw * 0.5f; gl[b][1] = gy - gh * 0.5f;
            gl[b][2] = gx + gw * 0.5f; gl[b][3] = gy + gh * 0.5f;
        }

        // ---- 2x2 IoU ----
        float iou[NB][NB];
        #pragma unroll
        for (int pi = 0; pi < NB; pi++) {
            #pragma unroll
            for (int gi = 0; gi < NB; gi++) {
                float ltx = fmaxf(pl[pi][0], gl[gi][0]);
                float lty = fmaxf(pl[pi][1], gl[gi][1]);
                float rbx = fminf(pl[pi][2], gl[gi][2]);
                float rby = fminf(pl[pi][3], gl[gi][3]);
                float wx = fmaxf(rbx - ltx, 0.0f);
                float wy = fmaxf(rby - lty, 0.0f);
                float inter = wx * wy;
                float aa = (pl[pi][2] - pl[pi][0]) * (pl[pi][3] - pl[pi][1]);
                float ab = (gl[gi][2] - gl[gi][0]) * (gl[gi][3] - gl[gi][1]);
                iou[pi][gi] = __fdividef(inter, aa + ab - inter + 1e-7f);
            }
        }

        int ind0 = (iou[1][0] > iou[0][0]) ? 1 : 0;
        int ind1 = (iou[1][1] > iou[0][1]) ? 1 : 0;

        bool same_g = (gbox[0][0] == gbox[1][0]) && (gbox[0][1] == gbox[1][1]) &&
                      (gbox[0][2] == gbox[1][2]) && (gbox[0][3] == gbox[1][3]);
        bool same_ind = (ind0 == ind1);

        float box_cell;
        if (same_g) {
            box_cell = box_loss_f(poff[ind0], gbox[0]);
        } else if (same_ind) {
            box_cell = box_loss_f(poff[0], gbox[0]) + box_loss_f(poff[1], gbox[1]);
        } else {
            box_cell = box_loss_f(poff[ind0], gbox[0]) + box_loss_f(poff[ind1], gbox[1]);
        }

        float conf_cell;
        if (same_g) {
            float x = ind1 ? pconf.y : pconf.x;
            conf_cell = fmaxf(x, 0.f) - x + __logf(bce_t(x));
        } else {
            conf_cell = fmaxf(pconf.x, 0.f) - pconf.x + fmaxf(pconf.y, 0.f) - pconf.y
                      + __logf(bce_t(pconf.x) * bce_t(pconf.y));
        }

        return L_BOX * box_cell + conf_cell + cls;
    } else {
        // ================= negative cell =================
        return L_NEG * (fmaxf(pconf.x, 0.f) + fmaxf(pconf.y, 0.f)
                        + __logf(bce_t(pconf.x) * bce_t(pconf.y)));
    }
}

__global__ void __launch_bounds__(TPB)
yolo_loss_kernel(const float* __restrict__ p, const float* __restrict__ g,
                 int ncells, float* __restrict__ out, float inv_nb) {
    // per-warp staging buffers: 32 cells x 30 floats per tensor
    __shared__ float4 sbuf[2][WARPS][240];   // 2 * 4 * 3840 B = 30720 B

    const int tid  = threadIdx.x;
    const int lane = tid & 31;
    const int wid  = tid >> 5;
    const int warpBase = blockIdx.x * TPB + wid * 32;
    float acc = 0.0f;

    if (warpBase + 32 <= ncells) {
        // -------- fast path: coalesced cp.async staging of 32 cells --------
        const float4* psrc = reinterpret_cast<const float4*>(p + (size_t)warpBase * DCH);
        const float4* gsrc = reinterpret_cast<const float4*>(g + (size_t)warpBase * DCH);
        uint32_t pdst = (uint32_t)__cvta_generic_to_shared(&sbuf[0][wid][0]);
        uint32_t gdst = (uint32_t)__cvta_generic_to_shared(&sbuf[1][wid][0]);
        #pragma unroll
        for (int k = 0; k < 8; k++) {
            int i = lane + 32 * k;
            if (i < 240) {
                cp_async16(pdst + i * 16, psrc + i);
                cp_async16(gdst + i * 16, gsrc + i);
            }
        }
        cp_async_wait_all();
        __syncwarp();

        const float* pcell = reinterpret_cast<const float*>(&sbuf[0][wid][0]) + lane * DCH;
        const float* gcell = reinterpret_cast<const float*>(&sbuf[1][wid][0]) + lane * DCH;
        acc = cell_loss(pcell, gcell, warpBase + lane);
    } else if (warpBase + lane < ncells) {
        // -------- tail path: direct global loads --------
        int idx = warpBase + lane;
        acc = cell_loss(p + (size_t)idx * DCH, g + (size_t)idx * DCH, idx);
    }

    // ---- deterministic block reduction ----
    #pragma unroll
    for (int o = 16; o > 0; o >>= 1)
        acc += __shfl_down_sync(0xffffffffu, acc, o);

    __shared__ float warp_sums[WARPS];
    if (lane == 0) warp_sums[wid] = acc;
    __syncthreads();

    if (tid == 0) {
        float v = 0.0f;
        #pragma unroll
        for (int w = 0; w < WARPS; w++) v += warp_sums[w];
        g_partials[blockIdx.x] = (double)v;
    }

    // ---- last-block finalization (deterministic fixed-order sum) ----
    __shared__ bool isLast;
    if (tid == 0) {
        __threadfence();
        unsigned int v = atomicAdd(&g_count, 1u);
        isLast = (v == gridDim.x - 1);
    }
    __syncthreads();

    if (isLast) {
        __shared__ double sh[TPB];
        double s = 0.0;
        for (int i = tid; i < (int)gridDim.x; i += TPB)
            s += g_partials[i];
        sh[tid] = s;
        __syncthreads();
        #pragma unroll
        for (int strideR = TPB / 2; strideR > 0; strideR >>= 1) {
            if (tid < strideR) sh[tid] += sh[tid + strideR];
            __syncthreads();
        }
        if (tid == 0) {
            out[0] = (float)(sh[0] * (double)inv_nb);
            g_count = 0;   // reset for next graph replay
        }
    }
}

extern "C" void kernel_launch(void* const* d_in, const int* in_sizes, int n_in,
                              void* d_out, int out_size) {
    const float* p = (const float*)d_in[0];
    const float* g = (const float*)d_in[1];
    float* out = (float*)d_out;

    int ncells = in_sizes[0] / DCH;                 // B * 49
    int batch  = ncells / (GRID_N * GRID_N);        // B
    int nblocks = (ncells + TPB - 1) / TPB;
    if (nblocks > MAX_BLOCKS) nblocks = MAX_BLOCKS; // ncells<=1M: never hit

    yolo_loss_kernel<<<nblocks, TPB>>>(p, g, ncells, out, 1.0f / (float)batch);
}

// round 8
// speedup vs baseline: 1.1882x; 1.1882x over previous
#include <cuda_runtime.h>
#include <cstdint>

#define GRID_N   7
#define NB       2
#define NC       20
#define IS       8
#define DCH      30
#define L_BOX    5.0f
#define L_NEG    0.5f

#define TPB      128
#define WARPS    (TPB / 32)
#define NBLOCKS  444            // 148 SMs x 3 blocks (smem-limited) = one wave
#define MAX_BLOCKS 1024

// per tile: 32 cells x 30 floats = 960 floats = 240 float4 per tensor
#define T4       240

__device__ double g_partials[MAX_BLOCKS];
__device__ unsigned int g_count = 0;

__device__ __forceinline__ void cp_async16(uint32_t dst, const void* src) {
    asm volatile("cp.async.cg.shared.global [%0], [%1], 16;\n" :: "r"(dst), "l"(src));
}
__device__ __forceinline__ void cp_commit() {
    asm volatile("cp.async.commit_group;\n" ::: "memory");
}
__device__ __forceinline__ void cp_wait1() {
    asm volatile("cp.async.wait_group 1;\n" ::: "memory");
}
__device__ __forceinline__ void cp_wait0() {
    asm volatile("cp.async.wait_group 0;\n" ::: "memory");
}

__device__ __forceinline__ float bce_t(float x) {           // 1 + exp(-|x|)
    return 1.0f + __expf(-fabsf(x));
}

__device__ __forceinline__ float box_loss_f(const float* pb, const float* gb) {
    float dx = pb[0] - gb[0];
    float dy = pb[1] - gb[1];
    float sw = sqrtf(fabsf(pb[2])) - sqrtf(gb[2]);
    float sh = sqrtf(fabsf(pb[3])) - sqrtf(gb[3]);
    return dx * dx + dy * dy + sw * sw + sh * sh;
}

// pc/gc point at one cell's 30 floats (smem in fast path, gmem in tail path).
__device__ __forceinline__ float cell_loss(const float* __restrict__ pc,
                                           const float* __restrict__ gc,
                                           int cellIdx) {
    const float2* pc2 = reinterpret_cast<const float2*>(pc);
    const float2* gc2 = reinterpret_cast<const float2*>(gc);
    float2 pb0 = pc2[0], pb1 = pc2[1], pb2v = pc2[2], pb3 = pc2[3];
    float2 gb0 = gc2[0], gb1 = gc2[1], gb2v = gc2[2], gb3 = gc2[3];
    float2 pconf = pc2[4];
    float2 gconf = gc2[4];

    if (gconf.x > 0.0f) {
        float pv[IS] = {pb0.x, pb0.y, pb1.x, pb1.y, pb2v.x, pb2v.y, pb3.x, pb3.y};
        float gv[IS] = {gb0.x, gb0.y, gb1.x, gb1.y, gb2v.x, gb2v.y, gb3.x, gb3.y};

        // ---- classification: linear part + single log of product ----
        const float2* pcl2 = reinterpret_cast<const float2*>(pc + NB * 5);
        const float2* gcl2 = reinterpret_cast<const float2*>(gc + NB * 5);
        float lin = 0.0f;
        float prod = 1.0f;
        #pragma unroll
        for (int i = 0; i < NC / 2; i++) {
            float2 a = pcl2[i];
            float2 b = gcl2[i];
            lin  += fmaxf(a.x, 0.f) - a.x * b.x + fmaxf(a.y, 0.f) - a.y * b.y;
            prod *= bce_t(a.x) * bce_t(a.y);
        }
        float cls = lin + __logf(prod);

        int cell = cellIdx % (GRID_N * GRID_N);
        float col = (float)(cell % GRID_N);
        float row = (float)(cell / GRID_N);

        float poff[NB][4], gbox[NB][4];
        #pragma unroll
        for (int b = 0; b < NB; b++) {
            poff[b][0] = __fdividef(1.0f, 1.0f + __expf(-pv[4 * b + 0]));
            poff[b][1] = __fdividef(1.0f, 1.0f + __expf(-pv[4 * b + 1]));
            poff[b][2] = pv[4 * b + 2];
            poff[b][3] = pv[4 * b + 3];
            gbox[b][0] = gv[4 * b + 0];
            gbox[b][1] = gv[4 * b + 1];
            gbox[b][2] = gv[4 * b + 2];
            gbox[b][3] = gv[4 * b + 3];
        }

        float pl[NB][4], gl[NB][4];
        #pragma unroll
        for (int b = 0; b < NB; b++) {
            float cx = (poff[b][0] + col) * (1.0f / GRID_N);
            float cy = (poff[b][1] + row) * (1.0f / GRID_N);
            float w  = poff[b][2], h = poff[b][3];
            pl[b][0] = cx - w * 0.5f; pl[b][1] = cy - h * 0.5f;
            pl[b][2] = cx + w * 0.5f; pl[b][3] = cy + h * 0.5f;
            float gx = (gbox[b][0] + col) * (1.0f / GRID_N);
            float gy = (gbox[b][1] + row) * (1.0f / GRID_N);
            float gw = gbox[b][2], gh = gbox[b][3];
            gl[b][0] = gx - gw * 0.5f; gl[b][1] = gy - gh * 0.5f;
            gl[b][2] = gx + gw * 0.5f; gl[b][3] = gy + gh * 0.5f;
        }

        float iou[NB][NB];
        #pragma unroll
        for (int pi = 0; pi < NB; pi++) {
            #pragma unroll
            for (int gi = 0; gi < NB; gi++) {
                float ltx = fmaxf(pl[pi][0], gl[gi][0]);
                float lty = fmaxf(pl[pi][1], gl[gi][1]);
                float rbx = fminf(pl[pi][2], gl[gi][2]);
                float rby = fminf(pl[pi][3], gl[gi][3]);
                float wx = fmaxf(rbx - ltx, 0.0f);
                float wy = fmaxf(rby - lty, 0.0f);
                float inter = wx * wy;
                float aa = (pl[pi][2] - pl[pi][0]) * (pl[pi][3] - pl[pi][1]);
                float ab = (gl[gi][2] - gl[gi][0]) * (gl[gi][3] - gl[gi][1]);
                iou[pi][gi] = __fdividef(inter, aa + ab - inter + 1e-7f);
            }
        }

        int ind0 = (iou[1][0] > iou[0][0]) ? 1 : 0;
        int ind1 = (iou[1][1] > iou[0][1]) ? 1 : 0;

        bool same_g = (gbox[0][0] == gbox[1][0]) && (gbox[0][1] == gbox[1][1]) &&
                      (gbox[0][2] == gbox[1][2]) && (gbox[0][3] == gbox[1][3]);
        bool same_ind = (ind0 == ind1);

        float box_cell;
        if (same_g) {
            box_cell = box_loss_f(poff[ind0], gbox[0]);
        } else if (same_ind) {
            box_cell = box_loss_f(poff[0], gbox[0]) + box_loss_f(poff[1], gbox[1]);
        } else {
            box_cell = box_loss_f(poff[ind0], gbox[0]) + box_loss_f(poff[ind1], gbox[1]);
        }

        float conf_cell;
        if (same_g) {
            float x = ind1 ? pconf.y : pconf.x;
            conf_cell = fmaxf(x, 0.f) - x + __logf(bce_t(x));
        } else {
            conf_cell = fmaxf(pconf.x, 0.f) - pconf.x + fmaxf(pconf.y, 0.f) - pconf.y
                      + __logf(bce_t(pconf.x) * bce_t(pconf.y));
        }

        return L_BOX * box_cell + conf_cell + cls;
    } else {
        return L_NEG * (fmaxf(pconf.x, 0.f) + fmaxf(pconf.y, 0.f)
                        + __logf(bce_t(pconf.x) * bce_t(pconf.y)));
    }
}

// issue one tile's staging loads (p then g), lane-partitioned, and commit
__device__ __forceinline__ void stage_tile(uint32_t dst, const float* __restrict__ p,
                                           const float* __restrict__ g,
                                           int tile, int lane) {
    const float4* psrc = reinterpret_cast<const float4*>(p + (size_t)tile * 32 * DCH);
    const float4* gsrc = reinterpret_cast<const float4*>(g + (size_t)tile * 32 * DCH);
    #pragma unroll
    for (int k = 0; k < 8; k++) {
        int i = lane + 32 * k;
        if (i < T4) {
            cp_async16(dst + i * 16, psrc + i);
            cp_async16(dst + (T4 + i) * 16, gsrc + i);
        }
    }
    cp_commit();
}

__global__ void __launch_bounds__(TPB)
yolo_loss_kernel(const float* __restrict__ p, const float* __restrict__ g,
                 int ncells, float* __restrict__ out, float inv_nb) {
    // per-warp double buffer: [stage][p(240) | g(240)] float4
    __shared__ float4 sbuf[WARPS][2][2 * T4];    // 4 * 2 * 480 * 16 = 61440 B

    const int tid  = threadIdx.x;
    const int lane = tid & 31;
    const int wid  = tid >> 5;
    const int warpGlobal = blockIdx.x * WARPS + wid;
    const int nwarps = gridDim.x * WARPS;
    const int ntiles = ncells >> 5;              // full 32-cell tiles

    uint32_t buf0 = (uint32_t)__cvta_generic_to_shared(&sbuf[wid][0][0]);
    uint32_t buf1 = (uint32_t)__cvta_generic_to_shared(&sbuf[wid][1][0]);

    float acc = 0.0f;

    // ---- prologue: prefetch first tile ----
    int t = warpGlobal;
    if (t < ntiles) stage_tile(buf0, p, g, t, lane);

    int cur = 0;
    for (; t < ntiles; t += nwarps) {
        int tn = t + nwarps;
        bool pf = (tn < ntiles);
        if (pf) stage_tile(cur ? buf0 : buf1, p, g, tn, lane);

        if (pf) cp_wait1(); else cp_wait0();
        __syncwarp();

        const float* base = reinterpret_cast<const float*>(&sbuf[wid][cur][0]);
        const float* pcell = base + lane * DCH;
        const float* gcell = base + 4 * T4 + lane * DCH;    // g starts after 960 floats
        acc += cell_loss(pcell, gcell, t * 32 + lane);

        __syncwarp();          // all lanes done reading before buffer is reused
        cur ^= 1;
    }

    // ---- tail cells (ncells not multiple of 32): warp 0 of block 0 ----
    if (blockIdx.x == 0 && wid == 0) {
        int idx = ntiles * 32 + lane;
        if (idx < ncells)
            acc += cell_loss(p + (size_t)idx * DCH, g + (size_t)idx * DCH, idx);
    }

    // ---- deterministic block reduction ----
    #pragma unroll
    for (int o = 16; o > 0; o >>= 1)
        acc += __shfl_down_sync(0xffffffffu, acc, o);

    __shared__ float warp_sums[WARPS];
    if (lane == 0) warp_sums[wid] = acc;
    __syncthreads();

    if (tid == 0) {
        float v = 0.0f;
        #pragma unroll
        for (int w = 0; w < WARPS; w++) v += warp_sums[w];
        g_partials[blockIdx.x] = (double)v;
    }

    // ---- last-block finalization (deterministic fixed-order sum) ----
    __shared__ bool isLast;
    if (tid == 0) {
        __threadfence();
        unsigned int v = atomicAdd(&g_count, 1u);
        isLast = (v == gridDim.x - 1);
    }
    __syncthreads();

    if (isLast) {
        __shared__ double sh[TPB];
        double s = 0.0;
        for (int i = tid; i < (int)gridDim.x; i += TPB)
            s += g_partials[i];
        sh[tid] = s;
        __syncthreads();
        #pragma unroll
        for (int strideR = TPB / 2; strideR > 0; strideR >>= 1) {
            if (tid < strideR) sh[tid] += sh[tid + strideR];
            __syncthreads();
        }
        if (tid == 0) {
            out[0] = (float)(sh[0] * (double)inv_nb);
            g_count = 0;   // reset for next graph replay
        }
    }
}

extern "C" void kernel_launch(void* const* d_in, const int* in_sizes, int n_in,
                              void* d_out, int out_size) {
    const float* p = (const float*)d_in[0];
    const float* g = (const float*)d_in[1];
    float* out = (float*)d_out;

    int ncells = in_sizes[0] / DCH;                 // B * 49
    int batch  = ncells / (GRID_N * GRID_N);        // B
    int ntiles = ncells >> 5;

    int nblocks = NBLOCKS;
    int needed = (ntiles + WARPS - 1) / WARPS;
    if (needed < 1) needed = 1;
    if (nblocks > needed) nblocks = needed;         // small inputs: shrink grid
    if (nblocks > MAX_BLOCKS) nblocks = MAX_BLOCKS;

    yolo_loss_kernel<<<nblocks, TPB>>>(p, g, ncells, out, 1.0f / (float)batch);
}